// round 2
// baseline (speedup 1.0000x reference)
#include <cuda_runtime.h>
#include <math.h>

#define N_NODES 100000
#define N_EDGES 1600000
#define NFEAT 128
#define NHID 64
#define NCLASS 40

// ---- scratch (no allocation allowed; __device__ globals) ----
__device__ __align__(16) float g_deg[N_NODES];      // degree
__device__ __align__(16) float g_dinv[N_NODES];     // deg^{-1/2} incl self-loop
__device__ __align__(16) float g_A[N_NODES * NHID]; // g = dinv * (x@W)
__device__ __align__(16) float g_B[N_NODES * NHID]; // scatter accumulator
__device__ __align__(16) float g_C[N_NODES * NHID]; // post-activation features

// ------------------------------------------------------- f32x2 helpers
__device__ __forceinline__ unsigned long long pack2(float a, float b) {
    unsigned long long r;
    asm("mov.b64 %0, {%1, %2};" : "=l"(r) : "f"(a), "f"(b));
    return r;
}
__device__ __forceinline__ unsigned long long ffma2(unsigned long long a,
                                                    unsigned long long b,
                                                    unsigned long long c) {
    unsigned long long d;
    asm("fma.rn.f32x2 %0, %1, %2, %3;" : "=l"(d) : "l"(a), "l"(b), "l"(c));
    return d;
}
__device__ __forceinline__ unsigned long long fmul2(unsigned long long a,
                                                    unsigned long long b) {
    unsigned long long d;
    asm("mul.rn.f32x2 %0, %1, %2;" : "=l"(d) : "l"(a), "l"(b));
    return d;
}

// ---------------------------------------------------------------- utilities
__global__ void zero_kernel(float4* p, int n4) {
    int i = blockIdx.x * blockDim.x + threadIdx.x;
    if (i < n4) p[i] = make_float4(0.f, 0.f, 0.f, 0.f);
}

__global__ void count_deg_kernel(const int* __restrict__ dst) {
    int e = blockIdx.x * blockDim.x + threadIdx.x;
    if (e < N_EDGES) atomicAdd(&g_deg[dst[e]], 1.0f);
}

__global__ void dinv_kernel() {
    int i = blockIdx.x * blockDim.x + threadIdx.x;
    if (i < N_NODES) g_dinv[i] = rsqrtf(g_deg[i] + 1.0f); // +1 self-loop
}

// ------------------------------------------------------------------- GEMM
// out[row, :] = dinv[row] * (X[row, :] @ W)  ; W is K x M row-major.
// One thread per row; W in smem read via 128-bit LDS; packed f32x2 FMA.
template <int K, int M>
__global__ void __launch_bounds__(128, 5) gemm_scale_kernel(
    const float* __restrict__ X, const float* __restrict__ W,
    float* __restrict__ out)
{
    __shared__ __align__(16) float Ws[K * M];
    for (int i = threadIdx.x; i < K * M / 4; i += 128)
        reinterpret_cast<float4*>(Ws)[i] =
            __ldg(&reinterpret_cast<const float4*>(W)[i]);
    __syncthreads();

    int row = blockIdx.x * 128 + threadIdx.x;
    if (row >= N_NODES) return;

    unsigned long long acc[M / 2];
#pragma unroll
    for (int i = 0; i < M / 2; i++) acc[i] = 0ull;

    const float4* x4 = reinterpret_cast<const float4*>(X + (size_t)row * K);
#pragma unroll 1
    for (int k4 = 0; k4 < K / 4; k4++) {
        float4 xv = __ldg(&x4[k4]);
        unsigned long long xp[4];
        xp[0] = pack2(xv.x, xv.x);
        xp[1] = pack2(xv.y, xv.y);
        xp[2] = pack2(xv.z, xv.z);
        xp[3] = pack2(xv.w, xv.w);
#pragma unroll
        for (int kk = 0; kk < 4; kk++) {
            const ulonglong2* wrow =
                reinterpret_cast<const ulonglong2*>(&Ws[(k4 * 4 + kk) * M]);
#pragma unroll
            for (int m4 = 0; m4 < M / 4; m4++) {
                ulonglong2 w = wrow[m4];
                acc[2 * m4]     = ffma2(xp[kk], w.x, acc[2 * m4]);
                acc[2 * m4 + 1] = ffma2(xp[kk], w.y, acc[2 * m4 + 1]);
            }
        }
    }

    float s = g_dinv[row];
    unsigned long long sp = pack2(s, s);
    ulonglong2* o2 = reinterpret_cast<ulonglong2*>(out + (size_t)row * M);
#pragma unroll
    for (int m4 = 0; m4 < M / 4; m4++) {
        ulonglong2 r;
        r.x = fmul2(acc[2 * m4], sp);
        r.y = fmul2(acc[2 * m4 + 1], sp);
        o2[m4] = r;
    }
}

// ----------------------------------------------------------------- scatter
__device__ __forceinline__ void red_add_v4(float* p, float4 v) {
    asm volatile("red.global.add.v4.f32 [%0], {%1, %2, %3, %4};"
                 :: "l"(p), "f"(v.x), "f"(v.y), "f"(v.z), "f"(v.w)
                 : "memory");
}

// acc[dst] += g[src] over 64-float rows; 8 threads/edge, 32B per thread
__global__ void scatter64_kernel(const float4* __restrict__ g, float* acc,
                                 const int* __restrict__ src,
                                 const int* __restrict__ dst)
{
    int tid = blockIdx.x * blockDim.x + threadIdx.x;
    int e = tid >> 3;
    int j = tid & 7;           // 2 float4 per thread: indices 2j, 2j+1
    if (e >= N_EDGES) return;
    int s = __ldg(&src[e]);
    int d = __ldg(&dst[e]);
    float4 v0 = __ldg(&g[(size_t)s * 16 + 2 * j]);
    float4 v1 = __ldg(&g[(size_t)s * 16 + 2 * j + 1]);
    float* base = acc + (size_t)d * 64 + j * 8;
    red_add_v4(base, v0);
    red_add_v4(base + 4, v1);
}

// acc[dst] += g[src] over 40-float rows; 5 threads/edge, 32B per thread
__global__ void scatter40_kernel(const float4* __restrict__ g, float* acc,
                                 const int* __restrict__ src,
                                 const int* __restrict__ dst)
{
    int tid = blockIdx.x * blockDim.x + threadIdx.x;
    int e = tid / 5;
    int j = tid - e * 5;       // 2 float4 per thread: indices 2j, 2j+1
    if (e >= N_EDGES) return;
    int s = __ldg(&src[e]);
    int d = __ldg(&dst[e]);
    float4 v0 = __ldg(&g[(size_t)s * 10 + 2 * j]);
    float4 v1 = __ldg(&g[(size_t)s * 10 + 2 * j + 1]);
    float* base = acc + (size_t)d * 40 + j * 8;
    red_add_v4(base, v0);
    red_add_v4(base + 4, v1);
}

// ------------------------------------------------------- post-aggregation
// C = relu(dinv * (B + A) + b)   over N_NODES x 64
__global__ void post_relu_kernel(const float4* __restrict__ A,
                                 const float4* __restrict__ B,
                                 const float* __restrict__ bias,
                                 float4* __restrict__ C)
{
    int idx = blockIdx.x * blockDim.x + threadIdx.x; // over N_NODES*16
    if (idx >= N_NODES * 16) return;
    int row = idx >> 4;
    int m4 = idx & 15;
    float s = __ldg(&g_dinv[row]);
    float4 a = A[idx], b = B[idx];
    float4 bb = __ldg(&reinterpret_cast<const float4*>(bias)[m4]);
    float4 r;
    r.x = fmaxf(fmaf(s, a.x + b.x, bb.x), 0.f);
    r.y = fmaxf(fmaf(s, a.y + b.y, bb.y), 0.f);
    r.z = fmaxf(fmaf(s, a.z + b.z, bb.z), 0.f);
    r.w = fmaxf(fmaf(s, a.w + b.w, bb.w), 0.f);
    C[idx] = r;
}

// --------------------------------------------- final: bias + log_softmax
__global__ void final_lsm_kernel(const float* __restrict__ A,
                                 const float* __restrict__ B,
                                 const float* __restrict__ b3,
                                 float* __restrict__ out)
{
    int warp = (blockIdx.x * blockDim.x + threadIdx.x) >> 5;
    int lane = threadIdx.x & 31;
    if (warp >= N_NODES) return;
    float s = g_dinv[warp];
    size_t base = (size_t)warp * 40;

    float v0 = s * (A[base + lane] + B[base + lane]) + __ldg(&b3[lane]);
    float v1 = -1e30f;
    if (lane < 8)
        v1 = s * (A[base + 32 + lane] + B[base + 32 + lane]) + __ldg(&b3[32 + lane]);

    float m = fmaxf(v0, v1);
#pragma unroll
    for (int off = 16; off > 0; off >>= 1)
        m = fmaxf(m, __shfl_xor_sync(0xFFFFFFFFu, m, off));

    float e = __expf(v0 - m) + ((lane < 8) ? __expf(v1 - m) : 0.f);
#pragma unroll
    for (int off = 16; off > 0; off >>= 1)
        e += __shfl_xor_sync(0xFFFFFFFFu, e, off);

    float ls = __logf(e);
    out[base + lane] = v0 - m - ls;
    if (lane < 8) out[base + 32 + lane] = v1 - m - ls;
}

// ------------------------------------------------------------------ launch
extern "C" void kernel_launch(void* const* d_in, const int* in_sizes, int n_in,
                              void* d_out, int out_size)
{
    const float* x   = (const float*)d_in[0];
    const int* ei    = (const int*)d_in[1];
    const float* W1  = (const float*)d_in[2];
    const float* b1  = (const float*)d_in[3];
    const float* W2  = (const float*)d_in[4];
    const float* b2  = (const float*)d_in[5];
    const float* W3  = (const float*)d_in[6];
    const float* b3  = (const float*)d_in[7];
    float* out       = (float*)d_out;

    const int* src = ei;
    const int* dst = ei + N_EDGES;

    float* A; cudaGetSymbolAddress((void**)&A, g_A);
    float* B; cudaGetSymbolAddress((void**)&B, g_B);
    float* C; cudaGetSymbolAddress((void**)&C, g_C);
    float* D; cudaGetSymbolAddress((void**)&D, g_deg);

    const int TPB = 256;
    // degrees -> dinv
    zero_kernel<<<(N_NODES / 4 + TPB - 1) / TPB, TPB>>>((float4*)D, N_NODES / 4);
    count_deg_kernel<<<(N_EDGES + TPB - 1) / TPB, TPB>>>(dst);
    dinv_kernel<<<(N_NODES + TPB - 1) / TPB, TPB>>>();

    const int n4_64 = N_NODES * NHID / 4;
    const int n4_40 = N_NODES * NCLASS / 4;
    const int gemm_blocks = (N_NODES + 127) / 128;
    const int sc64_blocks = (N_EDGES * 8 + TPB - 1) / TPB;
    const int sc40_blocks = (N_EDGES * 5 + TPB - 1) / TPB;
    const int post_blocks = (N_NODES * 16 + TPB - 1) / TPB;

    // ---- layer 1 ----
    gemm_scale_kernel<NFEAT, NHID><<<gemm_blocks, 128>>>(x, W1, A);
    zero_kernel<<<(n4_64 + TPB - 1) / TPB, TPB>>>((float4*)B, n4_64);
    scatter64_kernel<<<sc64_blocks, TPB>>>((const float4*)A, B, src, dst);
    post_relu_kernel<<<post_blocks, TPB>>>((const float4*)A, (const float4*)B, b1, (float4*)C);

    // ---- layer 2 ----
    gemm_scale_kernel<NHID, NHID><<<gemm_blocks, 128>>>(C, W2, A);
    zero_kernel<<<(n4_64 + TPB - 1) / TPB, TPB>>>((float4*)B, n4_64);
    scatter64_kernel<<<sc64_blocks, TPB>>>((const float4*)A, B, src, dst);
    post_relu_kernel<<<post_blocks, TPB>>>((const float4*)A, (const float4*)B, b2, (float4*)C);

    // ---- layer 3 ----
    gemm_scale_kernel<NHID, NCLASS><<<gemm_blocks, 128>>>(C, W3, A);
    zero_kernel<<<(n4_40 + TPB - 1) / TPB, TPB>>>((float4*)B, n4_40);
    scatter40_kernel<<<sc40_blocks, TPB>>>((const float4*)A, B, src, dst);
    final_lsm_kernel<<<(N_NODES * 32 + TPB - 1) / TPB, TPB>>>(A, B, b3, out);
}

// round 3
// speedup vs baseline: 1.7538x; 1.7538x over previous
#include <cuda_runtime.h>
#include <math.h>

#define N_NODES 100000
#define N_EDGES 1600000
#define NFEAT 128
#define NHID 64
#define NCLASS 40

#define SCAN_BLK 1024
#define NB ((N_NODES + SCAN_BLK - 1) / SCAN_BLK)   // 98

// ---- scratch (__device__ globals; no allocation allowed) ----
__device__ float g_dinv[N_NODES];
__device__ __align__(16) float g_A[N_NODES * NHID];  // g = dinv * (X@W)
__device__ __align__(16) float g_L[N_NODES * NHID];  // logits buffer (layer 3)
__device__ __align__(16) float g_C[N_NODES * NHID];  // post-activation features
__device__ int g_cnt[N_NODES];
__device__ int g_scan[N_NODES];
__device__ int g_bsum[NB];
__device__ int g_rowptr[N_NODES + 1];
__device__ int g_cursor[N_NODES];
__device__ int g_csr[N_EDGES];

// ------------------------------------------------------------ CSR build
__global__ void zero_cnt_kernel() {
    int i = blockIdx.x * blockDim.x + threadIdx.x;
    if (i < N_NODES) g_cnt[i] = 0;
}

__global__ void hist_kernel(const int* __restrict__ dst) {
    int e = blockIdx.x * blockDim.x + threadIdx.x;
    if (e < N_EDGES) atomicAdd(&g_cnt[dst[e]], 1);
}

__global__ void dinv_kernel() {
    int i = blockIdx.x * blockDim.x + threadIdx.x;
    if (i < N_NODES) g_dinv[i] = rsqrtf((float)g_cnt[i] + 1.0f); // +1 self-loop
}

__global__ void scan1_kernel() {      // grid NB, block 1024
    __shared__ int sm[2][SCAN_BLK];
    int t = threadIdx.x;
    int i = blockIdx.x * SCAN_BLK + t;
    int v = (i < N_NODES) ? g_cnt[i] : 0;
    sm[0][t] = v;
    __syncthreads();
    int pi = 0;
#pragma unroll
    for (int off = 1; off < SCAN_BLK; off <<= 1) {
        int x = sm[pi][t];
        if (t >= off) x += sm[pi][t - off];
        sm[pi ^ 1][t] = x;
        __syncthreads();
        pi ^= 1;
    }
    int incl = sm[pi][t];
    if (i < N_NODES) g_scan[i] = incl - v;       // exclusive
    if (t == SCAN_BLK - 1) g_bsum[blockIdx.x] = incl;
}

__global__ void scan2_kernel() {      // 1 block, thread 0 sequential over 98
    if (threadIdx.x == 0) {
        int run = 0;
        for (int b = 0; b < NB; b++) { int t = g_bsum[b]; g_bsum[b] = run; run += t; }
    }
}

__global__ void scan3_kernel() {
    int i = blockIdx.x * blockDim.x + threadIdx.x;
    if (i < N_NODES) {
        int r = g_scan[i] + g_bsum[i >> 10];
        g_rowptr[i] = r;
        g_cursor[i] = r;
    }
    if (i == 0) g_rowptr[N_NODES] = N_EDGES;
}

__global__ void fill_kernel(const int* __restrict__ src,
                            const int* __restrict__ dst) {
    int e = blockIdx.x * blockDim.x + threadIdx.x;
    if (e < N_EDGES) {
        int d = dst[e];
        int pos = atomicAdd(&g_cursor[d], 1);
        g_csr[pos] = src[e];
    }
}

// ------------------------------------------------------------------- GEMM
// out[row, :] = dinv[row] * (X[row, :] @ W)  ; W is K x M row-major.
template <int K, int M>
__global__ void __launch_bounds__(128) gemm_scale_kernel(
    const float* __restrict__ X, const float* __restrict__ W,
    float* __restrict__ out)
{
    __shared__ float Ws[K * M];
    for (int i = threadIdx.x; i < K * M; i += 128) Ws[i] = W[i];
    __syncthreads();

    int row = blockIdx.x * 128 + threadIdx.x;
    if (row >= N_NODES) return;

    float acc[M];
#pragma unroll
    for (int m = 0; m < M; m++) acc[m] = 0.f;

    const float4* x4 = reinterpret_cast<const float4*>(X + (size_t)row * K);
#pragma unroll 1
    for (int k4 = 0; k4 < K / 4; k4++) {
        float4 xv = __ldg(&x4[k4]);
        const float* w0 = &Ws[(k4 * 4 + 0) * M];
        const float* w1 = &Ws[(k4 * 4 + 1) * M];
        const float* w2 = &Ws[(k4 * 4 + 2) * M];
        const float* w3 = &Ws[(k4 * 4 + 3) * M];
#pragma unroll
        for (int m = 0; m < M; m++) {
            float a = acc[m];
            a = fmaf(xv.x, w0[m], a);
            a = fmaf(xv.y, w1[m], a);
            a = fmaf(xv.z, w2[m], a);
            a = fmaf(xv.w, w3[m], a);
            acc[m] = a;
        }
    }

    float s = g_dinv[row];
    float4* o4 = reinterpret_cast<float4*>(out + (size_t)row * M);
#pragma unroll
    for (int m4 = 0; m4 < M / 4; m4++)
        o4[m4] = make_float4(acc[4 * m4 + 0] * s, acc[4 * m4 + 1] * s,
                             acc[4 * m4 + 2] * s, acc[4 * m4 + 3] * s);
}

// ------------------------------------------------------- fused gather
__device__ __forceinline__ float4 add4(float4 a, float4 b) {
    return make_float4(a.x + b.x, a.y + b.y, a.z + b.z, a.w + b.w);
}

// C[row] = relu(dinv[row] * (sum_{e in csr[row]} g[src_e] + g[row]) + bias)
// 16 threads per row, one float4 per thread.
__global__ void gather_relu64_kernel(const float4* __restrict__ g,
                                     const float* __restrict__ bias,
                                     float4* __restrict__ C)
{
    int tid = blockIdx.x * blockDim.x + threadIdx.x;
    int row = tid >> 4;
    int j = tid & 15;
    if (row >= N_NODES) return;
    int beg = g_rowptr[row], end = g_rowptr[row + 1];

    float4 a0 = make_float4(0.f, 0.f, 0.f, 0.f);
    float4 a1 = make_float4(0.f, 0.f, 0.f, 0.f);
    int e = beg;
    for (; e + 1 < end; e += 2) {
        int s0 = __ldg(&g_csr[e]);
        int s1 = __ldg(&g_csr[e + 1]);
        a0 = add4(a0, __ldg(&g[(size_t)s0 * 16 + j]));
        a1 = add4(a1, __ldg(&g[(size_t)s1 * 16 + j]));
    }
    if (e < end) {
        int s = __ldg(&g_csr[e]);
        a0 = add4(a0, __ldg(&g[(size_t)s * 16 + j]));
    }
    float4 acc = add4(add4(a0, a1), __ldg(&g[(size_t)row * 16 + j]));
    float s = g_dinv[row];
    float4 bb = __ldg(&reinterpret_cast<const float4*>(bias)[j]);
    float4 r;
    r.x = fmaxf(fmaf(s, acc.x, bb.x), 0.f);
    r.y = fmaxf(fmaf(s, acc.y, bb.y), 0.f);
    r.z = fmaxf(fmaf(s, acc.z, bb.z), 0.f);
    r.w = fmaxf(fmaf(s, acc.w, bb.w), 0.f);
    C[(size_t)row * 16 + j] = r;
}

// L[row] = dinv[row] * (sum g40[src_e] + g40[row]) + b3   (no activation)
// 10 threads per row, one float4 per thread.
__global__ void gather_logits40_kernel(const float4* __restrict__ g,
                                       const float* __restrict__ b3,
                                       float4* __restrict__ L)
{
    int tid = blockIdx.x * blockDim.x + threadIdx.x;
    int row = tid / 10;
    int j = tid - row * 10;
    if (row >= N_NODES) return;
    int beg = g_rowptr[row], end = g_rowptr[row + 1];

    float4 a0 = make_float4(0.f, 0.f, 0.f, 0.f);
    float4 a1 = make_float4(0.f, 0.f, 0.f, 0.f);
    int e = beg;
    for (; e + 1 < end; e += 2) {
        int s0 = __ldg(&g_csr[e]);
        int s1 = __ldg(&g_csr[e + 1]);
        a0 = add4(a0, __ldg(&g[(size_t)s0 * 10 + j]));
        a1 = add4(a1, __ldg(&g[(size_t)s1 * 10 + j]));
    }
    if (e < end) {
        int s = __ldg(&g_csr[e]);
        a0 = add4(a0, __ldg(&g[(size_t)s * 10 + j]));
    }
    float4 acc = add4(add4(a0, a1), __ldg(&g[(size_t)row * 10 + j]));
    float s = g_dinv[row];
    float4 bb = __ldg(&reinterpret_cast<const float4*>(b3)[j]);
    float4 r;
    r.x = fmaf(s, acc.x, bb.x);
    r.y = fmaf(s, acc.y, bb.y);
    r.z = fmaf(s, acc.z, bb.z);
    r.w = fmaf(s, acc.w, bb.w);
    L[(size_t)row * 10 + j] = r;
}

// --------------------------------------------- final log_softmax (warp/row)
__global__ void final_lsm_kernel(const float* __restrict__ L,
                                 float* __restrict__ out)
{
    int warp = (blockIdx.x * blockDim.x + threadIdx.x) >> 5;
    int lane = threadIdx.x & 31;
    if (warp >= N_NODES) return;
    size_t base = (size_t)warp * 40;

    float v0 = L[base + lane];
    float v1 = (lane < 8) ? L[base + 32 + lane] : -1e30f;

    float m = fmaxf(v0, v1);
#pragma unroll
    for (int off = 16; off > 0; off >>= 1)
        m = fmaxf(m, __shfl_xor_sync(0xFFFFFFFFu, m, off));

    float e = __expf(v0 - m) + ((lane < 8) ? __expf(v1 - m) : 0.f);
#pragma unroll
    for (int off = 16; off > 0; off >>= 1)
        e += __shfl_xor_sync(0xFFFFFFFFu, e, off);

    float ls = __logf(e);
    out[base + lane] = v0 - m - ls;
    if (lane < 8) out[base + 32 + lane] = v1 - m - ls;
}

// ------------------------------------------------------------------ launch
extern "C" void kernel_launch(void* const* d_in, const int* in_sizes, int n_in,
                              void* d_out, int out_size)
{
    const float* x   = (const float*)d_in[0];
    const int* ei    = (const int*)d_in[1];
    const float* W1  = (const float*)d_in[2];
    const float* b1  = (const float*)d_in[3];
    const float* W2  = (const float*)d_in[4];
    const float* b2  = (const float*)d_in[5];
    const float* W3  = (const float*)d_in[6];
    const float* b3  = (const float*)d_in[7];
    float* out       = (float*)d_out;

    const int* src = ei;
    const int* dst = ei + N_EDGES;

    float* A; cudaGetSymbolAddress((void**)&A, g_A);
    float* L; cudaGetSymbolAddress((void**)&L, g_L);
    float* C; cudaGetSymbolAddress((void**)&C, g_C);

    const int TPB = 256;
    const int nodeBlocks = (N_NODES + TPB - 1) / TPB;
    const int edgeBlocks = (N_EDGES + TPB - 1) / TPB;
    const int gemm_blocks = (N_NODES + 127) / 128;
    const int g64_blocks = (N_NODES * 16 + TPB - 1) / TPB;
    const int g40_blocks = (N_NODES * 10 + TPB - 1) / TPB;

    // ---- CSR build + dinv ----
    zero_cnt_kernel<<<nodeBlocks, TPB>>>();
    hist_kernel<<<edgeBlocks, TPB>>>(dst);
    dinv_kernel<<<nodeBlocks, TPB>>>();
    scan1_kernel<<<NB, SCAN_BLK>>>();
    scan2_kernel<<<1, 32>>>();
    scan3_kernel<<<nodeBlocks, TPB>>>();
    fill_kernel<<<edgeBlocks, TPB>>>(src, dst);

    // ---- layer 1 ----
    gemm_scale_kernel<NFEAT, NHID><<<gemm_blocks, 128>>>(x, W1, A);
    gather_relu64_kernel<<<g64_blocks, TPB>>>((const float4*)A, b1, (float4*)C);

    // ---- layer 2 ----
    gemm_scale_kernel<NHID, NHID><<<gemm_blocks, 128>>>(C, W2, A);
    gather_relu64_kernel<<<g64_blocks, TPB>>>((const float4*)A, b2, (float4*)C);

    // ---- layer 3 ----
    gemm_scale_kernel<NHID, NCLASS><<<gemm_blocks, 128>>>(C, W3, A);
    gather_logits40_kernel<<<g40_blocks, TPB>>>((const float4*)A, b3, (float4*)L);
    final_lsm_kernel<<<(N_NODES * 32 + TPB - 1) / TPB, TPB>>>(L, out);
}

// round 4
// speedup vs baseline: 2.1694x; 1.2369x over previous
#include <cuda_runtime.h>
#include <math.h>

#define N_NODES 100000
#define N_EDGES 1600000
#define NFEAT 128
#define NHID 64
#define NCLASS 40

#define SCAN_BLK 1024
#define NB ((N_NODES + SCAN_BLK - 1) / SCAN_BLK)   // 98

// ---- scratch (__device__ globals; no allocation allowed) ----
__device__ float g_dinv[N_NODES];
__device__ __align__(16) float g_A[N_NODES * NHID];  // g = dinv * (X@W)
__device__ __align__(16) float g_L[N_NODES * NHID];  // logits buffer (layer 3)
__device__ __align__(16) float g_C[N_NODES * NHID];  // post-activation features
__device__ int g_cnt[N_NODES];
__device__ int g_scan[N_NODES];
__device__ int g_bsum[NB];
__device__ int g_rowptr[N_NODES + 1];
__device__ int g_cursor[N_NODES];
__device__ int g_csr[N_EDGES];

// ------------------------------------------------------------ CSR build
__global__ void zero_cnt_kernel() {
    int i = blockIdx.x * blockDim.x + threadIdx.x;
    if (i < N_NODES) g_cnt[i] = 0;
}

__global__ void hist_kernel(const int* __restrict__ dst) {
    int e = blockIdx.x * blockDim.x + threadIdx.x;
    if (e < N_EDGES) atomicAdd(&g_cnt[dst[e]], 1);
}

__global__ void dinv_kernel() {
    int i = blockIdx.x * blockDim.x + threadIdx.x;
    if (i < N_NODES) g_dinv[i] = rsqrtf((float)g_cnt[i] + 1.0f); // +1 self-loop
}

__global__ void scan1_kernel() {      // grid NB, block 1024
    __shared__ int sm[2][SCAN_BLK];
    int t = threadIdx.x;
    int i = blockIdx.x * SCAN_BLK + t;
    int v = (i < N_NODES) ? g_cnt[i] : 0;
    sm[0][t] = v;
    __syncthreads();
    int pi = 0;
#pragma unroll
    for (int off = 1; off < SCAN_BLK; off <<= 1) {
        int x = sm[pi][t];
        if (t >= off) x += sm[pi][t - off];
        sm[pi ^ 1][t] = x;
        __syncthreads();
        pi ^= 1;
    }
    int incl = sm[pi][t];
    if (i < N_NODES) g_scan[i] = incl - v;       // exclusive
    if (t == SCAN_BLK - 1) g_bsum[blockIdx.x] = incl;
}

__global__ void scan2_kernel() {
    if (threadIdx.x == 0) {
        int run = 0;
        for (int b = 0; b < NB; b++) { int t = g_bsum[b]; g_bsum[b] = run; run += t; }
    }
}

__global__ void scan3_kernel() {
    int i = blockIdx.x * blockDim.x + threadIdx.x;
    if (i < N_NODES) {
        int r = g_scan[i] + g_bsum[i >> 10];
        g_rowptr[i] = r;
        g_cursor[i] = r;
    }
    if (i == 0) g_rowptr[N_NODES] = N_EDGES;
}

__global__ void fill_kernel(const int* __restrict__ src,
                            const int* __restrict__ dst) {
    int e = blockIdx.x * blockDim.x + threadIdx.x;
    if (e < N_EDGES) {
        int d = dst[e];
        int pos = atomicAdd(&g_cursor[d], 1);
        g_csr[pos] = src[e];
    }
}

// ------------------------------------------------------------------- GEMM
// Tiled register-blocked SGEMM with fused dinv row scaling.
// Block tile: 64 rows x M cols. Threads: (M/4) x 8; each thread 8 rows x 4 cols.
template <int K, int M>
__global__ void __launch_bounds__((M / 4) * 8) gemm_tiled_kernel(
    const float* __restrict__ X, const float* __restrict__ W,
    float* __restrict__ out)
{
    constexpr int KC = 16;                 // k-chunk
    constexpr int ROWS = 64;
    constexpr int NT = (M / 4) * 8;
    constexpr int XS_STRIDE = ROWS + 4;    // keep 16B alignment, skew banks

    __shared__ __align__(16) float Xs[KC * XS_STRIDE];
    __shared__ __align__(16) float Ws[KC * M];

    const int tid = threadIdx.x;
    const int tx = tid % (M / 4);          // col group (4 cols)
    const int ty = tid / (M / 4);          // row group (8 rows)
    const int rowBase = blockIdx.x * ROWS;

    float acc[8][4];
#pragma unroll
    for (int r = 0; r < 8; r++)
#pragma unroll
        for (int c = 0; c < 4; c++) acc[r][c] = 0.f;

    const float4* X4 = reinterpret_cast<const float4*>(X);
    const float4* W4 = reinterpret_cast<const float4*>(W);

#pragma unroll 1
    for (int c0 = 0; c0 < K; c0 += KC) {
        // load X chunk [64 rows x KC] transposed into Xs[kk][row]
#pragma unroll 1
        for (int idx = tid; idx < ROWS * KC / 4; idx += NT) {
            int rl = idx >> 2;             // local row 0..63
            int k4 = idx & 3;              // which float4 within chunk
            int row = rowBase + rl;
            float4 v = (row < N_NODES)
                ? __ldg(&X4[(size_t)row * (K / 4) + c0 / 4 + k4])
                : make_float4(0.f, 0.f, 0.f, 0.f);
            Xs[(k4 * 4 + 0) * XS_STRIDE + rl] = v.x;
            Xs[(k4 * 4 + 1) * XS_STRIDE + rl] = v.y;
            Xs[(k4 * 4 + 2) * XS_STRIDE + rl] = v.z;
            Xs[(k4 * 4 + 3) * XS_STRIDE + rl] = v.w;
        }
        // load W chunk [KC x M]
#pragma unroll 1
        for (int idx = tid; idx < KC * M / 4; idx += NT) {
            int kk = idx / (M / 4);
            int m4 = idx % (M / 4);
            reinterpret_cast<float4*>(Ws)[kk * (M / 4) + m4] =
                __ldg(&W4[(size_t)(c0 + kk) * (M / 4) + m4]);
        }
        __syncthreads();

#pragma unroll
        for (int kk = 0; kk < KC; kk++) {
            float4 b = *reinterpret_cast<const float4*>(&Ws[kk * M + tx * 4]);
            float4 a0 = *reinterpret_cast<const float4*>(&Xs[kk * XS_STRIDE + ty * 8]);
            float4 a1 = *reinterpret_cast<const float4*>(&Xs[kk * XS_STRIDE + ty * 8 + 4]);
            float a[8] = {a0.x, a0.y, a0.z, a0.w, a1.x, a1.y, a1.z, a1.w};
#pragma unroll
            for (int r = 0; r < 8; r++) {
                acc[r][0] = fmaf(a[r], b.x, acc[r][0]);
                acc[r][1] = fmaf(a[r], b.y, acc[r][1]);
                acc[r][2] = fmaf(a[r], b.z, acc[r][2]);
                acc[r][3] = fmaf(a[r], b.w, acc[r][3]);
            }
        }
        __syncthreads();
    }

    // epilogue: scale by dinv[row], 128-bit stores
#pragma unroll
    for (int r = 0; r < 8; r++) {
        int row = rowBase + ty * 8 + r;
        if (row < N_NODES) {
            float s = __ldg(&g_dinv[row]);
            float4 o = make_float4(acc[r][0] * s, acc[r][1] * s,
                                   acc[r][2] * s, acc[r][3] * s);
            reinterpret_cast<float4*>(out)[(size_t)row * (M / 4) + tx] = o;
        }
    }
}

// ------------------------------------------------------- fused gather
__device__ __forceinline__ float4 add4(float4 a, float4 b) {
    return make_float4(a.x + b.x, a.y + b.y, a.z + b.z, a.w + b.w);
}

// C[row] = relu(dinv[row] * (sum_{e in csr[row]} g[src_e] + g[row]) + bias)
__global__ void gather_relu64_kernel(const float4* __restrict__ g,
                                     const float* __restrict__ bias,
                                     float4* __restrict__ C)
{
    int tid = blockIdx.x * blockDim.x + threadIdx.x;
    int row = tid >> 4;
    int j = tid & 15;
    if (row >= N_NODES) return;
    int beg = g_rowptr[row], end = g_rowptr[row + 1];

    float4 a0 = make_float4(0.f, 0.f, 0.f, 0.f);
    float4 a1 = make_float4(0.f, 0.f, 0.f, 0.f);
    int e = beg;
    for (; e + 1 < end; e += 2) {
        int s0 = __ldg(&g_csr[e]);
        int s1 = __ldg(&g_csr[e + 1]);
        a0 = add4(a0, __ldg(&g[(size_t)s0 * 16 + j]));
        a1 = add4(a1, __ldg(&g[(size_t)s1 * 16 + j]));
    }
    if (e < end) {
        int s = __ldg(&g_csr[e]);
        a0 = add4(a0, __ldg(&g[(size_t)s * 16 + j]));
    }
    float4 acc = add4(add4(a0, a1), __ldg(&g[(size_t)row * 16 + j]));
    float s = g_dinv[row];
    float4 bb = __ldg(&reinterpret_cast<const float4*>(bias)[j]);
    float4 r;
    r.x = fmaxf(fmaf(s, acc.x, bb.x), 0.f);
    r.y = fmaxf(fmaf(s, acc.y, bb.y), 0.f);
    r.z = fmaxf(fmaf(s, acc.z, bb.z), 0.f);
    r.w = fmaxf(fmaf(s, acc.w, bb.w), 0.f);
    C[(size_t)row * 16 + j] = r;
}

// L[row] = dinv[row] * (sum g40[src_e] + g40[row]) + b3   (no activation)
__global__ void gather_logits40_kernel(const float4* __restrict__ g,
                                       const float* __restrict__ b3,
                                       float4* __restrict__ L)
{
    int tid = blockIdx.x * blockDim.x + threadIdx.x;
    int row = tid / 10;
    int j = tid - row * 10;
    if (row >= N_NODES) return;
    int beg = g_rowptr[row], end = g_rowptr[row + 1];

    float4 a0 = make_float4(0.f, 0.f, 0.f, 0.f);
    float4 a1 = make_float4(0.f, 0.f, 0.f, 0.f);
    int e = beg;
    for (; e + 1 < end; e += 2) {
        int s0 = __ldg(&g_csr[e]);
        int s1 = __ldg(&g_csr[e + 1]);
        a0 = add4(a0, __ldg(&g[(size_t)s0 * 10 + j]));
        a1 = add4(a1, __ldg(&g[(size_t)s1 * 10 + j]));
    }
    if (e < end) {
        int s = __ldg(&g_csr[e]);
        a0 = add4(a0, __ldg(&g[(size_t)s * 10 + j]));
    }
    float4 acc = add4(add4(a0, a1), __ldg(&g[(size_t)row * 10 + j]));
    float s = g_dinv[row];
    float4 bb = __ldg(&reinterpret_cast<const float4*>(b3)[j]);
    float4 r;
    r.x = fmaf(s, acc.x, bb.x);
    r.y = fmaf(s, acc.y, bb.y);
    r.z = fmaf(s, acc.z, bb.z);
    r.w = fmaf(s, acc.w, bb.w);
    L[(size_t)row * 10 + j] = r;
}

// --------------------------------------------- final log_softmax (warp/row)
__global__ void final_lsm_kernel(const float* __restrict__ L,
                                 float* __restrict__ out)
{
    int warp = (blockIdx.x * blockDim.x + threadIdx.x) >> 5;
    int lane = threadIdx.x & 31;
    if (warp >= N_NODES) return;
    size_t base = (size_t)warp * 40;

    float v0 = L[base + lane];
    float v1 = (lane < 8) ? L[base + 32 + lane] : -1e30f;

    float m = fmaxf(v0, v1);
#pragma unroll
    for (int off = 16; off > 0; off >>= 1)
        m = fmaxf(m, __shfl_xor_sync(0xFFFFFFFFu, m, off));

    float e = __expf(v0 - m) + ((lane < 8) ? __expf(v1 - m) : 0.f);
#pragma unroll
    for (int off = 16; off > 0; off >>= 1)
        e += __shfl_xor_sync(0xFFFFFFFFu, e, off);

    float ls = __logf(e);
    out[base + lane] = v0 - m - ls;
    if (lane < 8) out[base + 32 + lane] = v1 - m - ls;
}

// ------------------------------------------------------------------ launch
extern "C" void kernel_launch(void* const* d_in, const int* in_sizes, int n_in,
                              void* d_out, int out_size)
{
    const float* x   = (const float*)d_in[0];
    const int* ei    = (const int*)d_in[1];
    const float* W1  = (const float*)d_in[2];
    const float* b1  = (const float*)d_in[3];
    const float* W2  = (const float*)d_in[4];
    const float* b2  = (const float*)d_in[5];
    const float* W3  = (const float*)d_in[6];
    const float* b3  = (const float*)d_in[7];
    float* out       = (float*)d_out;

    const int* src = ei;
    const int* dst = ei + N_EDGES;

    float* A; cudaGetSymbolAddress((void**)&A, g_A);
    float* L; cudaGetSymbolAddress((void**)&L, g_L);
    float* C; cudaGetSymbolAddress((void**)&C, g_C);

    const int TPB = 256;
    const int nodeBlocks = (N_NODES + TPB - 1) / TPB;
    const int edgeBlocks = (N_EDGES + TPB - 1) / TPB;
    const int tile_blocks = (N_NODES + 63) / 64;   // 1563
    const int g64_blocks = (N_NODES * 16 + TPB - 1) / TPB;
    const int g40_blocks = (N_NODES * 10 + TPB - 1) / TPB;

    // ---- CSR build + dinv ----
    zero_cnt_kernel<<<nodeBlocks, TPB>>>();
    hist_kernel<<<edgeBlocks, TPB>>>(dst);
    dinv_kernel<<<nodeBlocks, TPB>>>();
    scan1_kernel<<<NB, SCAN_BLK>>>();
    scan2_kernel<<<1, 32>>>();
    scan3_kernel<<<nodeBlocks, TPB>>>();
    fill_kernel<<<edgeBlocks, TPB>>>(src, dst);

    // ---- layer 1 ----
    gemm_tiled_kernel<NFEAT, NHID><<<tile_blocks, 128>>>(x, W1, A);
    gather_relu64_kernel<<<g64_blocks, TPB>>>((const float4*)A, b1, (float4*)C);

    // ---- layer 2 ----
    gemm_tiled_kernel<NHID, NHID><<<tile_blocks, 128>>>(C, W2, A);
    gather_relu64_kernel<<<g64_blocks, TPB>>>((const float4*)A, b2, (float4*)C);

    // ---- layer 3 ----
    gemm_tiled_kernel<NHID, NCLASS><<<tile_blocks, 80>>>(C, W3, A);
    gather_logits40_kernel<<<g40_blocks, TPB>>>((const float4*)A, b3, (float4*)L);
    final_lsm_kernel<<<(N_NODES * 32 + TPB - 1) / TPB, TPB>>>(L, out);
}

// round 5
// speedup vs baseline: 2.2516x; 1.0379x over previous
#include <cuda_runtime.h>
#include <cuda_fp16.h>
#include <math.h>

#define N_NODES 100000
#define N_EDGES 1600000
#define NFEAT 128
#define NHID 64
#define NCLASS 40

#define SCAN_BLK 1024
#define NB ((N_NODES + SCAN_BLK - 1) / SCAN_BLK)   // 98

// ---- scratch (__device__ globals; no allocation allowed) ----
__device__ float g_dinv[N_NODES];
__device__ __align__(16) __half g_Ah[N_NODES * NHID]; // fp16 g = dinv*(X@W)
__device__ __align__(16) float g_L[N_NODES * NHID];   // logits buffer (layer 3)
__device__ __align__(16) float g_C[N_NODES * NHID];   // post-activation features
__device__ int g_cnt[N_NODES];
__device__ int g_scan[N_NODES];
__device__ int g_bsum[NB];
__device__ int g_rowptr[N_NODES + 1];
__device__ int g_cursor[N_NODES];
__device__ int g_csr[N_EDGES];

// ------------------------------------------------------------ CSR build
__global__ void zero_cnt_kernel() {
    int i = blockIdx.x * blockDim.x + threadIdx.x;
    if (i < N_NODES) g_cnt[i] = 0;
}

__global__ void hist_kernel(const int* __restrict__ dst) {
    int e = blockIdx.x * blockDim.x + threadIdx.x;
    if (e < N_EDGES) atomicAdd(&g_cnt[dst[e]], 1);
}

__global__ void dinv_kernel() {
    int i = blockIdx.x * blockDim.x + threadIdx.x;
    if (i < N_NODES) g_dinv[i] = rsqrtf((float)g_cnt[i] + 1.0f); // +1 self-loop
}

__global__ void scan1_kernel() {      // grid NB, block 1024
    __shared__ int sm[2][SCAN_BLK];
    int t = threadIdx.x;
    int i = blockIdx.x * SCAN_BLK + t;
    int v = (i < N_NODES) ? g_cnt[i] : 0;
    sm[0][t] = v;
    __syncthreads();
    int pi = 0;
#pragma unroll
    for (int off = 1; off < SCAN_BLK; off <<= 1) {
        int x = sm[pi][t];
        if (t >= off) x += sm[pi][t - off];
        sm[pi ^ 1][t] = x;
        __syncthreads();
        pi ^= 1;
    }
    int incl = sm[pi][t];
    if (i < N_NODES) g_scan[i] = incl - v;       // exclusive
    if (t == SCAN_BLK - 1) g_bsum[blockIdx.x] = incl;
}

// parallel exclusive scan over the NB (=98) block sums, one 128-thread block
__global__ void scan2_kernel() {
    __shared__ int sm[2][128];
    int t = threadIdx.x;
    int v = (t < NB) ? g_bsum[t] : 0;
    sm[0][t] = v;
    __syncthreads();
    int pi = 0;
#pragma unroll
    for (int off = 1; off < 128; off <<= 1) {
        int x = sm[pi][t];
        if (t >= off) x += sm[pi][t - off];
        sm[pi ^ 1][t] = x;
        __syncthreads();
        pi ^= 1;
    }
    if (t < NB) g_bsum[t] = sm[pi][t] - v;       // exclusive
}

__global__ void scan3_kernel() {
    int i = blockIdx.x * blockDim.x + threadIdx.x;
    if (i < N_NODES) {
        int r = g_scan[i] + g_bsum[i >> 10];
        g_rowptr[i] = r;
        g_cursor[i] = r;
    }
    if (i == 0) g_rowptr[N_NODES] = N_EDGES;
}

__global__ void fill_kernel(const int* __restrict__ src,
                            const int* __restrict__ dst) {
    int e = blockIdx.x * blockDim.x + threadIdx.x;
    if (e < N_EDGES) {
        int d = dst[e];
        int pos = atomicAdd(&g_cursor[d], 1);
        g_csr[pos] = src[e];
    }
}

// ------------------------------------------------------------------- GEMM
// Tiled register-blocked SGEMM, fused dinv scaling, fp16 output.
// Block tile: 64 rows x M cols. Threads: (M/4) x 8; each thread 8 rows x 4 cols.
template <int K, int M>
__global__ void __launch_bounds__((M / 4) * 8) gemm_tiled_h_kernel(
    const float* __restrict__ X, const float* __restrict__ W,
    __half* __restrict__ out)
{
    constexpr int KC = 16;
    constexpr int ROWS = 64;
    constexpr int NT = (M / 4) * 8;
    constexpr int XS_STRIDE = ROWS + 4;

    __shared__ __align__(16) float Xs[KC * XS_STRIDE];
    __shared__ __align__(16) float Ws[KC * M];

    const int tid = threadIdx.x;
    const int tx = tid % (M / 4);
    const int ty = tid / (M / 4);
    const int rowBase = blockIdx.x * ROWS;

    float acc[8][4];
#pragma unroll
    for (int r = 0; r < 8; r++)
#pragma unroll
        for (int c = 0; c < 4; c++) acc[r][c] = 0.f;

    const float4* X4 = reinterpret_cast<const float4*>(X);
    const float4* W4 = reinterpret_cast<const float4*>(W);

#pragma unroll 1
    for (int c0 = 0; c0 < K; c0 += KC) {
#pragma unroll 1
        for (int idx = tid; idx < ROWS * KC / 4; idx += NT) {
            int rl = idx >> 2;
            int k4 = idx & 3;
            int row = rowBase + rl;
            float4 v = (row < N_NODES)
                ? __ldg(&X4[(size_t)row * (K / 4) + c0 / 4 + k4])
                : make_float4(0.f, 0.f, 0.f, 0.f);
            Xs[(k4 * 4 + 0) * XS_STRIDE + rl] = v.x;
            Xs[(k4 * 4 + 1) * XS_STRIDE + rl] = v.y;
            Xs[(k4 * 4 + 2) * XS_STRIDE + rl] = v.z;
            Xs[(k4 * 4 + 3) * XS_STRIDE + rl] = v.w;
        }
#pragma unroll 1
        for (int idx = tid; idx < KC * M / 4; idx += NT) {
            int kk = idx / (M / 4);
            int m4 = idx % (M / 4);
            reinterpret_cast<float4*>(Ws)[kk * (M / 4) + m4] =
                __ldg(&W4[(size_t)(c0 + kk) * (M / 4) + m4]);
        }
        __syncthreads();

#pragma unroll
        for (int kk = 0; kk < KC; kk++) {
            float4 b = *reinterpret_cast<const float4*>(&Ws[kk * M + tx * 4]);
            float4 a0 = *reinterpret_cast<const float4*>(&Xs[kk * XS_STRIDE + ty * 8]);
            float4 a1 = *reinterpret_cast<const float4*>(&Xs[kk * XS_STRIDE + ty * 8 + 4]);
            float a[8] = {a0.x, a0.y, a0.z, a0.w, a1.x, a1.y, a1.z, a1.w};
#pragma unroll
            for (int r = 0; r < 8; r++) {
                acc[r][0] = fmaf(a[r], b.x, acc[r][0]);
                acc[r][1] = fmaf(a[r], b.y, acc[r][1]);
                acc[r][2] = fmaf(a[r], b.z, acc[r][2]);
                acc[r][3] = fmaf(a[r], b.w, acc[r][3]);
            }
        }
        __syncthreads();
    }

    // epilogue: scale by dinv, convert to fp16, 64-bit stores
#pragma unroll
    for (int r = 0; r < 8; r++) {
        int row = rowBase + ty * 8 + r;
        if (row < N_NODES) {
            float s = __ldg(&g_dinv[row]);
            __half2 h0 = __float22half2_rn(make_float2(acc[r][0] * s, acc[r][1] * s));
            __half2 h1 = __float22half2_rn(make_float2(acc[r][2] * s, acc[r][3] * s));
            uint2 pack;
            pack.x = *reinterpret_cast<unsigned*>(&h0);
            pack.y = *reinterpret_cast<unsigned*>(&h1);
            reinterpret_cast<uint2*>(out)[(size_t)row * (M / 4) + tx] = pack;
        }
    }
}

// ------------------------------------------------------- fused gather
struct F8 { float v[8]; };
__device__ __forceinline__ void acc8(F8& a, uint4 p) {
    const __half2* h = reinterpret_cast<const __half2*>(&p);
#pragma unroll
    for (int q = 0; q < 4; q++) {
        float2 f = __half22float2(h[q]);
        a.v[2 * q]     += f.x;
        a.v[2 * q + 1] += f.y;
    }
}

// C[row] = relu(dinv[row]*(sum_{e} g[src_e] + g[row]) + bias), 64 wide.
// 8 threads per row, 8 features (16B fp16) per thread.
__global__ void gather_relu64_kernel(const uint4* __restrict__ g,
                                     const float* __restrict__ bias,
                                     float4* __restrict__ C)
{
    int tid = blockIdx.x * blockDim.x + threadIdx.x;
    int row = tid >> 3;
    int j = tid & 7;
    if (row >= N_NODES) return;
    int beg = g_rowptr[row], end = g_rowptr[row + 1];

    F8 a0, a1;
#pragma unroll
    for (int q = 0; q < 8; q++) { a0.v[q] = 0.f; a1.v[q] = 0.f; }

    int e = beg;
    for (; e + 1 < end; e += 2) {
        int s0 = __ldg(&g_csr[e]);
        int s1 = __ldg(&g_csr[e + 1]);
        acc8(a0, __ldg(&g[(size_t)s0 * 8 + j]));
        acc8(a1, __ldg(&g[(size_t)s1 * 8 + j]));
    }
    if (e < end) {
        int s = __ldg(&g_csr[e]);
        acc8(a0, __ldg(&g[(size_t)s * 8 + j]));
    }
    acc8(a0, __ldg(&g[(size_t)row * 8 + j]));   // self loop
#pragma unroll
    for (int q = 0; q < 8; q++) a0.v[q] += a1.v[q];

    float s = g_dinv[row];
    const float4* b4 = reinterpret_cast<const float4*>(bias);
    float4 bb0 = __ldg(&b4[2 * j]);
    float4 bb1 = __ldg(&b4[2 * j + 1]);
    float4 r0, r1;
    r0.x = fmaxf(fmaf(s, a0.v[0], bb0.x), 0.f);
    r0.y = fmaxf(fmaf(s, a0.v[1], bb0.y), 0.f);
    r0.z = fmaxf(fmaf(s, a0.v[2], bb0.z), 0.f);
    r0.w = fmaxf(fmaf(s, a0.v[3], bb0.w), 0.f);
    r1.x = fmaxf(fmaf(s, a0.v[4], bb1.x), 0.f);
    r1.y = fmaxf(fmaf(s, a0.v[5], bb1.y), 0.f);
    r1.z = fmaxf(fmaf(s, a0.v[6], bb1.z), 0.f);
    r1.w = fmaxf(fmaf(s, a0.v[7], bb1.w), 0.f);
    C[(size_t)row * 16 + 2 * j]     = r0;
    C[(size_t)row * 16 + 2 * j + 1] = r1;
}

// L[row] = dinv[row]*(sum g40[src_e] + g40[row]) + b3, 40 wide (fp32 out).
// 10 threads per row, 4 features (8B fp16) per thread.
__global__ void gather_logits40_kernel(const uint2* __restrict__ g,
                                       const float* __restrict__ b3,
                                       float4* __restrict__ L)
{
    int tid = blockIdx.x * blockDim.x + threadIdx.x;
    int row = tid / 10;
    int j = tid - row * 10;
    if (row >= N_NODES) return;
    int beg = g_rowptr[row], end = g_rowptr[row + 1];

    float a0 = 0.f, a1 = 0.f, a2 = 0.f, a3 = 0.f;
    int e = beg;
    for (; e < end; e++) {
        int s = __ldg(&g_csr[e]);
        uint2 p = __ldg(&g[(size_t)s * 10 + j]);
        float2 f0 = __half22float2(*reinterpret_cast<const __half2*>(&p.x));
        float2 f1 = __half22float2(*reinterpret_cast<const __half2*>(&p.y));
        a0 += f0.x; a1 += f0.y; a2 += f1.x; a3 += f1.y;
    }
    {
        uint2 p = __ldg(&g[(size_t)row * 10 + j]);   // self loop
        float2 f0 = __half22float2(*reinterpret_cast<const __half2*>(&p.x));
        float2 f1 = __half22float2(*reinterpret_cast<const __half2*>(&p.y));
        a0 += f0.x; a1 += f0.y; a2 += f1.x; a3 += f1.y;
    }
    float s = g_dinv[row];
    float4 bb = __ldg(&reinterpret_cast<const float4*>(b3)[j]);
    float4 r;
    r.x = fmaf(s, a0, bb.x);
    r.y = fmaf(s, a1, bb.y);
    r.z = fmaf(s, a2, bb.z);
    r.w = fmaf(s, a3, bb.w);
    L[(size_t)row * 10 + j] = r;
}

// --------------------------------------------- final log_softmax (warp/row)
__global__ void final_lsm_kernel(const float* __restrict__ L,
                                 float* __restrict__ out)
{
    int warp = (blockIdx.x * blockDim.x + threadIdx.x) >> 5;
    int lane = threadIdx.x & 31;
    if (warp >= N_NODES) return;
    size_t base = (size_t)warp * 40;

    float v0 = L[base + lane];
    float v1 = (lane < 8) ? L[base + 32 + lane] : -1e30f;

    float m = fmaxf(v0, v1);
#pragma unroll
    for (int off = 16; off > 0; off >>= 1)
        m = fmaxf(m, __shfl_xor_sync(0xFFFFFFFFu, m, off));

    float e = __expf(v0 - m) + ((lane < 8) ? __expf(v1 - m) : 0.f);
#pragma unroll
    for (int off = 16; off > 0; off >>= 1)
        e += __shfl_xor_sync(0xFFFFFFFFu, e, off);

    float ls = __logf(e);
    out[base + lane] = v0 - m - ls;
    if (lane < 8) out[base + 32 + lane] = v1 - m - ls;
}

// ------------------------------------------------------------------ launch
extern "C" void kernel_launch(void* const* d_in, const int* in_sizes, int n_in,
                              void* d_out, int out_size)
{
    const float* x   = (const float*)d_in[0];
    const int* ei    = (const int*)d_in[1];
    const float* W1  = (const float*)d_in[2];
    const float* b1  = (const float*)d_in[3];
    const float* W2  = (const float*)d_in[4];
    const float* b2  = (const float*)d_in[5];
    const float* W3  = (const float*)d_in[6];
    const float* b3  = (const float*)d_in[7];
    float* out       = (float*)d_out;

    const int* src = ei;
    const int* dst = ei + N_EDGES;

    __half* Ah; cudaGetSymbolAddress((void**)&Ah, g_Ah);
    float* L;   cudaGetSymbolAddress((void**)&L, g_L);
    float* C;   cudaGetSymbolAddress((void**)&C, g_C);

    const int TPB = 256;
    const int nodeBlocks = (N_NODES + TPB - 1) / TPB;
    const int edgeBlocks = (N_EDGES + TPB - 1) / TPB;
    const int tile_blocks = (N_NODES + 63) / 64;
    const int g64_blocks = (N_NODES * 8 + TPB - 1) / TPB;
    const int g40_blocks = (N_NODES * 10 + TPB - 1) / TPB;

    // ---- CSR build + dinv ----
    zero_cnt_kernel<<<nodeBlocks, TPB>>>();
    hist_kernel<<<edgeBlocks, TPB>>>(dst);
    dinv_kernel<<<nodeBlocks, TPB>>>();
    scan1_kernel<<<NB, SCAN_BLK>>>();
    scan2_kernel<<<1, 128>>>();
    scan3_kernel<<<nodeBlocks, TPB>>>();
    fill_kernel<<<edgeBlocks, TPB>>>(src, dst);

    // ---- layer 1 ----
    gemm_tiled_h_kernel<NFEAT, NHID><<<tile_blocks, 128>>>(x, W1, Ah);
    gather_relu64_kernel<<<g64_blocks, TPB>>>((const uint4*)Ah, b1, (float4*)C);

    // ---- layer 2 ----
    gemm_tiled_h_kernel<NHID, NHID><<<tile_blocks, 128>>>(C, W2, Ah);
    gather_relu64_kernel<<<g64_blocks, TPB>>>((const uint4*)Ah, b2, (float4*)C);

    // ---- layer 3 ----
    gemm_tiled_h_kernel<NHID, NCLASS><<<tile_blocks, 80>>>(C, W3, Ah);
    gather_logits40_kernel<<<g40_blocks, TPB>>>((const uint2*)Ah, b3, (float4*)L);
    final_lsm_kernel<<<(N_NODES * 32 + TPB - 1) / TPB, TPB>>>(L, out);
}